// round 14
// baseline (speedup 1.0000x reference)
#include <cuda_runtime.h>
#include <cuda_bf16.h>
#include <math.h>
#include <stdint.h>

// ---------------------------------------------------------------------------
// Problem constants
// ---------------------------------------------------------------------------
static constexpr int kN = 32;
static constexpr int kM = 32;
static constexpr int kP = 196;
static constexpr int kD = 768;
static constexpr float kMargin = 0.5f;
static constexpr float kEps = 1e-8f;

static constexpr int NN_PAIRS = kN * (kN - 1) / 2;      // 496
static constexpr int ND_PAIRS = kN * kM;                // 1024
static constexpr int TOTAL_PAIRS = NN_PAIRS + ND_PAIRS; // 1520
static constexpr int TOTAL_UNITS = TOTAL_PAIRS * 2;     // 3040 (pair x N-block)

static constexpr int KC = 64;            // k-chunk in bf16 halves (4 ks-steps)
static constexpr int NCHUNK = kD / KC;   // 12
static constexpr int STRIDE = 72;        // smem row stride in halves (144B: conflict-free ldmatrix)

// Dynamic smem layout (bytes): 2-stage A/B staging + epilogue scratch
static constexpr int TILE_BYTES = 128 * STRIDE * 2;              // 18432 per stage
static constexpr int OFF_A0     = 0;
static constexpr int OFF_A1     = OFF_A0 + TILE_BYTES;
static constexpr int OFF_B0     = OFF_A1 + TILE_BYTES;
static constexpr int OFF_B1     = OFF_B0 + TILE_BYTES;
static constexpr int OFF_PART   = OFF_B1 + TILE_BYTES;           // float[4][128]
static constexpr int OFF_CMAX   = OFF_PART + 2048;               // float[128]
static constexpr int OFF_RBUF   = OFF_CMAX + 512;                // float[8]
static constexpr int SMEM_BYTES = OFF_RBUF + 64;                 // 76352

// Scratch (device globals — no allocations). 16B-aligned for vector access.
__device__ __align__(16) __nv_bfloat16 g_n1b[kN * kP * kD];
__device__ __align__(16) __nv_bfloat16 g_n2b[kM * kP * kD];
__device__ float g_unit_loss[TOTAL_UNITS];

// ---------------------------------------------------------------------------
__device__ __forceinline__ uint32_t smem_u32(const void* p) {
    uint32_t a;
    asm("{ .reg .u64 t; cvta.to.shared.u64 t, %1; cvt.u32.u64 %0, t; }" : "=r"(a) : "l"(p));
    return a;
}

__device__ __forceinline__ void ldmatrix_x4(uint32_t& r0, uint32_t& r1,
                                            uint32_t& r2, uint32_t& r3, uint32_t addr) {
    asm volatile("ldmatrix.sync.aligned.m8n8.x4.shared.b16 {%0,%1,%2,%3}, [%4];"
                 : "=r"(r0), "=r"(r1), "=r"(r2), "=r"(r3) : "r"(addr));
}

__device__ __forceinline__ void mma_bf16(float* d, const uint32_t* a, uint32_t b0, uint32_t b1) {
    asm volatile(
        "mma.sync.aligned.m16n8k16.row.col.f32.bf16.bf16.f32 "
        "{%0,%1,%2,%3}, {%4,%5,%6,%7}, {%8,%9}, {%0,%1,%2,%3};"
        : "+f"(d[0]), "+f"(d[1]), "+f"(d[2]), "+f"(d[3])
        : "r"(a[0]), "r"(a[1]), "r"(a[2]), "r"(a[3]), "r"(b0), "r"(b1));
}

// cp.async 16B with zero-fill when invalid (src-size form)
__device__ __forceinline__ void cpa16(uint32_t dst, const void* src, bool valid) {
    int sz = valid ? 16 : 0;
    asm volatile("cp.async.cg.shared.global [%0], [%1], 16, %2;"
                 :: "r"(dst), "l"(src), "r"(sz) : "memory");
}
#define CPA_COMMIT() asm volatile("cp.async.commit_group;" ::: "memory")
#define CPA_WAIT0()  asm volatile("cp.async.wait_group 0;" ::: "memory")

// ---------------------------------------------------------------------------
// Kernel 1: row-wise L2 normalize, fp32 -> bf16
// ---------------------------------------------------------------------------
__global__ void normalize_kernel(const float* __restrict__ normal,
                                 const float* __restrict__ defect) {
    int row = blockIdx.x;
    const float* src;
    __nv_bfloat16* dst;
    if (row < kN * kP) {
        src = normal + (size_t)row * kD;
        dst = g_n1b + (size_t)row * kD;
    } else {
        int r = row - kN * kP;
        src = defect + (size_t)r * kD;
        dst = g_n2b + (size_t)r * kD;
    }
    int t = threadIdx.x;
    float v0 = src[t], v1 = src[t + 256], v2 = src[t + 512];
    float ss = v0 * v0 + v1 * v1 + v2 * v2;
    #pragma unroll
    for (int o = 16; o > 0; o >>= 1) ss += __shfl_xor_sync(0xffffffffu, ss, o);
    __shared__ float ws[8];
    __shared__ float s_scale;
    if ((t & 31) == 0) ws[t >> 5] = ss;
    __syncthreads();
    if (t == 0) {
        float tot = 0.f;
        #pragma unroll
        for (int w = 0; w < 8; w++) tot += ws[w];
        s_scale = 1.0f / (sqrtf(tot) + kEps);
    }
    __syncthreads();
    float s = s_scale;
    dst[t]       = __float2bfloat16(v0 * s);
    dst[t + 256] = __float2bfloat16(v1 * s);
    dst[t + 512] = __float2bfloat16(v2 * s);
}

// ---------------------------------------------------------------------------
__device__ __forceinline__ void decode_tri(int t, int& i, int& j) {
    float disc = (float)((2 * kN - 1) * (2 * kN - 1) - 8 * t);
    int ii = (int)((2.0f * kN - 1.0f - sqrtf(disc)) * 0.5f);
    while (ii > 0 && t < ii * (2 * kN - ii - 1) / 2) ii--;
    while (t >= (ii + 1) * (2 * kN - ii - 2) / 2 + (ii + 1)) ii++;
    int base = ii * (2 * kN - ii - 1) / 2;
    i = ii;
    j = ii + 1 + (t - base);
}

// ---------------------------------------------------------------------------
// Kernel 2: one CTA per (pair, N-block) unit. bf16 mma.sync GEMM + fused
// column-max + partial loss. The unit covers 128 q-columns and ALL p-rows
// (2 mb passes of 128), so its colmax is final and its loss partial is
// independent. Warp grid 4(M) x 2(N), warp tile 32x64, KC=64 chunks.
// ---------------------------------------------------------------------------
__global__ void __launch_bounds__(256, 2) pair_kernel() {
    extern __shared__ __align__(16) char sm[];
    float* s_part   = (float*)(sm + OFF_PART);   // [4][128]
    float* s_colmax = (float*)(sm + OFF_CMAX);   // [128]
    float* s_rbuf   = (float*)(sm + OFF_RBUF);   // [8]

    int tid = threadIdx.x;
    int lane = tid & 31;
    int wid = tid >> 5;
    int wy = wid >> 1;   // 0..3 -> M sub-block (32 rows)
    int wx = wid & 1;    // 0..1 -> N sub-block (64 cols)

    // Unit decode: pair + N-block
    int unitIdx = blockIdx.x;
    int pairIdx = unitIdx >> 1;
    int nb = unitIdx & 1;
    int bn0 = nb * 128;

    const __nv_bfloat16* A;
    const __nv_bfloat16* B;
    bool is_nn;
    if (pairIdx < NN_PAIRS) {
        is_nn = true;
        int i, j;
        decode_tri(pairIdx, i, j);
        A = g_n1b + (size_t)i * kP * kD;
        B = g_n1b + (size_t)j * kP * kD;
    } else {
        is_nn = false;
        int t = pairIdx - NN_PAIRS;
        A = g_n1b + (size_t)(t / kM) * kP * kD;
        B = g_n2b + (size_t)(t % kM) * kP * kD;
    }

    if (tid < 128) s_colmax[tid] = -1e30f;
    __syncthreads();

    // cp.async staging: per chunk, A/B = 128 rows x 64 halves = 1024 x 16B each.
    int ldRowB = tid >> 3;              // 0..31
    int ldSeg  = (tid & 7) * 8;         // halves offset within 64-half window

    uint32_t smA[2] = { smem_u32(sm + OFF_A0), smem_u32(sm + OFF_A1) };
    uint32_t smB[2] = { smem_u32(sm + OFF_B0), smem_u32(sm + OFF_B1) };
    uint32_t dOff[4];
    #pragma unroll
    for (int it = 0; it < 4; it++)
        dOff[it] = (uint32_t)(((ldRowB + it * 32) * STRIDE + ldSeg) * 2);

    // ldmatrix lane addressing (byte offsets within a staging buffer)
    int ar = lane & 15, ah = lane >> 4;
    uint32_t aOffB = (uint32_t)(((wy * 32 + ar) * STRIDE + ah * 8) * 2);
    int bq = lane >> 3, brr = lane & 7;
    uint32_t bOffB = (uint32_t)(((wx * 64 + ((bq >> 1) & 1) * 8 + brr) * STRIDE + (bq & 1) * 8) * 2);

    // N-tile validity at 16-col granularity (uniform per warp; fixed for unit)
    bool nval[4];
    #pragma unroll
    for (int ntp = 0; ntp < 4; ntp++) nval[ntp] = (bn0 + wx * 64 + ntp * 16) < kP;

    #pragma unroll 1
    for (int mb = 0; mb < 2; mb++) {
        int am0 = mb * 128;
        // M-tile validity at 16-row granularity (uniform per warp)
        bool mval[2];
        #pragma unroll
        for (int mt = 0; mt < 2; mt++) mval[mt] = (am0 + wy * 32 + mt * 16) < kP;
        bool anyM = mval[0];

        float acc[2][8][4];
        #pragma unroll
        for (int mt = 0; mt < 2; mt++)
            #pragma unroll
            for (int nt = 0; nt < 8; nt++)
                #pragma unroll
                for (int e = 0; e < 4; e++) acc[mt][nt][e] = 0.0f;

        // Preload chunk 0 into buffer 0
        {
            #pragma unroll
            for (int it = 0; it < 4; it++) {
                int r = am0 + ldRowB + it * 32;
                cpa16(smA[0] + dOff[it], A + (size_t)r * kD + ldSeg, r < kP);
            }
            #pragma unroll
            for (int it = 0; it < 4; it++) {
                int r = bn0 + ldRowB + it * 32;
                cpa16(smB[0] + dOff[it], B + (size_t)r * kD + ldSeg, r < kP);
            }
            CPA_COMMIT();
        }

        #pragma unroll 1
        for (int c = 0; c < NCHUNK; c++) {
            int b = c & 1;
            CPA_WAIT0();
            __syncthreads();   // buf c ready; all warps past mma(c-1)

            if (c + 1 < NCHUNK) {
                int nbuf = (c + 1) & 1;
                int k0 = (c + 1) * KC + ldSeg;
                #pragma unroll
                for (int it = 0; it < 4; it++) {
                    int r = am0 + ldRowB + it * 32;
                    cpa16(smA[nbuf] + dOff[it], A + (size_t)r * kD + k0, r < kP);
                }
                #pragma unroll
                for (int it = 0; it < 4; it++) {
                    int r = bn0 + ldRowB + it * 32;
                    cpa16(smB[nbuf] + dOff[it], B + (size_t)r * kD + k0, r < kP);
                }
                CPA_COMMIT();
            }

            if (anyM) {
                #pragma unroll
                for (int ks = 0; ks < 4; ks++) {
                    uint32_t a0[2][4];
                    #pragma unroll
                    for (int mt = 0; mt < 2; mt++)
                        if (mval[mt])
                            ldmatrix_x4(a0[mt][0], a0[mt][1], a0[mt][2], a0[mt][3],
                                        smA[b] + aOffB + (uint32_t)((mt * 16 * STRIDE + ks * 16) * 2));
                    #pragma unroll
                    for (int ntp = 0; ntp < 4; ntp++) {
                        if (nval[ntp]) {
                            uint32_t b0, b1, b2, b3;
                            ldmatrix_x4(b0, b1, b2, b3,
                                        smB[b] + bOffB + (uint32_t)((ntp * 16 * STRIDE + ks * 16) * 2));
                            #pragma unroll
                            for (int mt = 0; mt < 2; mt++) {
                                if (mval[mt]) {
                                    mma_bf16(acc[mt][ntp * 2 + 0], a0[mt], b0, b1);
                                    mma_bf16(acc[mt][ntp * 2 + 1], a0[mt], b2, b3);
                                }
                            }
                        }
                    }
                }
            }
        }
        __syncthreads();   // all mma done before s_part reuse

        // ----- Epilogue: column max over this pass's valid rows -----
        int rbase = am0 + wy * 32 + (lane >> 2);
        #pragma unroll
        for (int nt = 0; nt < 8; nt++) {
            if (!nval[nt >> 1]) continue;   // uniform across warps; cols never read
            float c0 = -1e30f, c1 = -1e30f;
            #pragma unroll
            for (int mt = 0; mt < 2; mt++) {
                int r1 = rbase + mt * 16;
                bool v1 = r1 < kP, v2 = (r1 + 8) < kP;
                const float* cc = acc[mt][nt];
                c0 = fmaxf(c0, fmaxf(v1 ? cc[0] : -1e30f, v2 ? cc[2] : -1e30f));
                c1 = fmaxf(c1, fmaxf(v1 ? cc[1] : -1e30f, v2 ? cc[3] : -1e30f));
            }
            #pragma unroll
            for (int o = 4; o <= 16; o <<= 1) {
                c0 = fmaxf(c0, __shfl_xor_sync(0xffffffffu, c0, o));
                c1 = fmaxf(c1, __shfl_xor_sync(0xffffffffu, c1, o));
            }
            if (lane < 4) {
                int col = wx * 64 + nt * 8 + 2 * lane;
                s_part[wy * 128 + col]     = c0;
                s_part[wy * 128 + col + 1] = c1;
            }
        }
        __syncthreads();
        if (tid < 128) {
            int q = bn0 + tid;
            if (q < kP) {
                float m = fmaxf(fmaxf(s_part[0 * 128 + tid], s_part[1 * 128 + tid]),
                                fmaxf(s_part[2 * 128 + tid], s_part[3 * 128 + tid]));
                s_colmax[tid] = fmaxf(s_colmax[tid], m);
            }
        }
        __syncthreads();
    }

    // ----- Partial loss over this unit's valid q, warp-shuffle reduce -----
    float v = 0.0f;
    if (tid < 128 && (bn0 + tid) < kP) {
        float m = s_colmax[tid];
        v = is_nn ? (1.0f - m) : fmaxf(m - kMargin, 0.0f);
    }
    #pragma unroll
    for (int o = 16; o > 0; o >>= 1) v += __shfl_xor_sync(0xffffffffu, v, o);
    if (lane == 0) s_rbuf[wid] = v;
    __syncthreads();
    if (tid == 0) {
        float tot = 0.f;
        #pragma unroll
        for (int w = 0; w < 8; w++) tot += s_rbuf[w];
        g_unit_loss[unitIdx] = tot;
    }
}

// ---------------------------------------------------------------------------
// Kernel 3: deterministic finalize over 3040 unit partials
// ---------------------------------------------------------------------------
__global__ void finalize_kernel(float* __restrict__ out) {
    int t = threadIdx.x;
    float pos = 0.f, neg = 0.f;
    for (int idx = t; idx < TOTAL_UNITS; idx += 256) {
        float v = g_unit_loss[idx];
        if ((idx >> 1) < NN_PAIRS) pos += v; else neg += v;
    }
    #pragma unroll
    for (int o = 16; o > 0; o >>= 1) {
        pos += __shfl_xor_sync(0xffffffffu, pos, o);
        neg += __shfl_xor_sync(0xffffffffu, neg, o);
    }
    __shared__ float sp[8], sn[8];
    if ((t & 31) == 0) { sp[t >> 5] = pos; sn[t >> 5] = neg; }
    __syncthreads();
    if (t == 0) {
        float ptot = 0.f, ntot = 0.f;
        #pragma unroll
        for (int w = 0; w < 8; w++) { ptot += sp[w]; ntot += sn[w]; }
        out[0] = ptot / (float)(NN_PAIRS * kP) + ntot / (float)(kN * kM * kP);
    }
}

// ---------------------------------------------------------------------------
extern "C" void kernel_launch(void* const* d_in, const int* in_sizes, int n_in,
                              void* d_out, int out_size) {
    const float* normal = (const float*)d_in[0];
    const float* defect = (const float*)d_in[1];
    float* out = (float*)d_out;

    cudaFuncSetAttribute(pair_kernel, cudaFuncAttributeMaxDynamicSharedMemorySize, SMEM_BYTES);

    normalize_kernel<<<(kN + kM) * kP, 256>>>(normal, defect);
    pair_kernel<<<TOTAL_UNITS, 256, SMEM_BYTES>>>();
    finalize_kernel<<<1, 256>>>(out);
}

// round 15
// speedup vs baseline: 1.0715x; 1.0715x over previous
#include <cuda_runtime.h>
#include <cuda_bf16.h>
#include <math.h>
#include <stdint.h>

// ---------------------------------------------------------------------------
// Problem constants
// ---------------------------------------------------------------------------
static constexpr int kN = 32;
static constexpr int kM = 32;
static constexpr int kP = 196;
static constexpr int kD = 768;
static constexpr float kMargin = 0.5f;
static constexpr float kEps = 1e-8f;

static constexpr int NN_PAIRS = kN * (kN - 1) / 2;      // 496
static constexpr int ND_PAIRS = kN * kM;                // 1024
static constexpr int TOTAL_PAIRS = NN_PAIRS + ND_PAIRS; // 1520

static constexpr int KC = 64;            // k-chunk in bf16 halves (4 ks-steps)
static constexpr int NCHUNK = kD / KC;   // 12
static constexpr int STRIDE = 72;        // smem row stride in halves (144B: conflict-free ldmatrix)

// Dynamic smem layout (bytes): 2-stage A(128 rows)/B(256 rows) + scratch
static constexpr int A_BYTES    = 128 * STRIDE * 2;              // 18432
static constexpr int B_BYTES    = 256 * STRIDE * 2;              // 36864
static constexpr int OFF_A0     = 0;
static constexpr int OFF_A1     = OFF_A0 + A_BYTES;
static constexpr int OFF_B0     = OFF_A1 + A_BYTES;              // 36864
static constexpr int OFF_B1     = OFF_B0 + B_BYTES;              // 73728
static constexpr int OFF_PART   = OFF_B1 + B_BYTES;              // 110592: float[4][256]
static constexpr int OFF_CMAX   = OFF_PART + 4096;               // 114688: float[256]
static constexpr int OFF_RBUF   = OFF_CMAX + 1024;               // 115712: float[16]
static constexpr int SMEM_BYTES = OFF_RBUF + 64;                 // 115776

// Scratch (device globals — no allocations). 16B-aligned for vector access.
__device__ __align__(16) __nv_bfloat16 g_n1b[kN * kP * kD];
__device__ __align__(16) __nv_bfloat16 g_n2b[kM * kP * kD];
__device__ float g_pair_loss[TOTAL_PAIRS];

// ---------------------------------------------------------------------------
__device__ __forceinline__ uint32_t smem_u32(const void* p) {
    uint32_t a;
    asm("{ .reg .u64 t; cvta.to.shared.u64 t, %1; cvt.u32.u64 %0, t; }" : "=r"(a) : "l"(p));
    return a;
}

__device__ __forceinline__ void ldmatrix_x4(uint32_t& r0, uint32_t& r1,
                                            uint32_t& r2, uint32_t& r3, uint32_t addr) {
    asm volatile("ldmatrix.sync.aligned.m8n8.x4.shared.b16 {%0,%1,%2,%3}, [%4];"
                 : "=r"(r0), "=r"(r1), "=r"(r2), "=r"(r3) : "r"(addr));
}

__device__ __forceinline__ void mma_bf16(float* d, const uint32_t* a, uint32_t b0, uint32_t b1) {
    asm volatile(
        "mma.sync.aligned.m16n8k16.row.col.f32.bf16.bf16.f32 "
        "{%0,%1,%2,%3}, {%4,%5,%6,%7}, {%8,%9}, {%0,%1,%2,%3};"
        : "+f"(d[0]), "+f"(d[1]), "+f"(d[2]), "+f"(d[3])
        : "r"(a[0]), "r"(a[1]), "r"(a[2]), "r"(a[3]), "r"(b0), "r"(b1));
}

// cp.async 16B with zero-fill when invalid (src-size form)
__device__ __forceinline__ void cpa16(uint32_t dst, const void* src, bool valid) {
    int sz = valid ? 16 : 0;
    asm volatile("cp.async.cg.shared.global [%0], [%1], 16, %2;"
                 :: "r"(dst), "l"(src), "r"(sz) : "memory");
}
#define CPA_COMMIT() asm volatile("cp.async.commit_group;" ::: "memory")
#define CPA_WAIT0()  asm volatile("cp.async.wait_group 0;" ::: "memory")

// ---------------------------------------------------------------------------
// Kernel 1: one warp per row L2 normalize, fp32 -> bf16 (no block barriers)
// ---------------------------------------------------------------------------
__global__ void normalize_kernel(const float* __restrict__ normal,
                                 const float* __restrict__ defect) {
    int row = (blockIdx.x * blockDim.x + threadIdx.x) >> 5;   // global warp id
    int lane = threadIdx.x & 31;

    const float* src;
    __nv_bfloat16* dst;
    if (row < kN * kP) {
        src = normal + (size_t)row * kD;
        dst = g_n1b + (size_t)row * kD;
    } else {
        int r = row - kN * kP;
        src = defect + (size_t)r * kD;
        dst = g_n2b + (size_t)r * kD;
    }

    float4 v[6];
    float ss = 0.f;
    #pragma unroll
    for (int k = 0; k < 6; k++) {
        v[k] = *(const float4*)(src + lane * 4 + k * 128);
        ss += v[k].x * v[k].x + v[k].y * v[k].y + v[k].z * v[k].z + v[k].w * v[k].w;
    }
    #pragma unroll
    for (int o = 16; o > 0; o >>= 1) ss += __shfl_xor_sync(0xffffffffu, ss, o);
    float s = 1.0f / (sqrtf(ss) + kEps);

    #pragma unroll
    for (int k = 0; k < 6; k++) {
        __nv_bfloat162 h0 = __floats2bfloat162_rn(v[k].x * s, v[k].y * s);
        __nv_bfloat162 h1 = __floats2bfloat162_rn(v[k].z * s, v[k].w * s);
        uint2 pk = make_uint2(*(uint32_t*)&h0, *(uint32_t*)&h1);
        *(uint2*)(dst + lane * 4 + k * 128) = pk;
    }
}

// ---------------------------------------------------------------------------
__device__ __forceinline__ void decode_tri(int t, int& i, int& j) {
    float disc = (float)((2 * kN - 1) * (2 * kN - 1) - 8 * t);
    int ii = (int)((2.0f * kN - 1.0f - sqrtf(disc)) * 0.5f);
    while (ii > 0 && t < ii * (2 * kN - ii - 1) / 2) ii--;
    while (t >= (ii + 1) * (2 * kN - ii - 2) / 2 + (ii + 1)) ii++;
    int base = ii * (2 * kN - ii - 1) / 2;
    i = ii;
    j = ii + 1 + (t - base);
}

// ---------------------------------------------------------------------------
// Kernel 2: ONE 512-thread CTA per pair. Block covers 128(M) x 256(N) per
// pass, 2 mb passes. Warp grid 4(wy) x 4(wx), warp tile 32x64
// (2 mt x 8 nt m16n8 frags). KC=64 chunks -> 24 sync iterations per pair.
// ---------------------------------------------------------------------------
__global__ void __launch_bounds__(512, 1) pair_kernel() {
    extern __shared__ __align__(16) char sm[];
    float* s_part   = (float*)(sm + OFF_PART);   // [4][256]
    float* s_colmax = (float*)(sm + OFF_CMAX);   // [256]
    float* s_rbuf   = (float*)(sm + OFF_RBUF);   // [16]

    int tid = threadIdx.x;
    int lane = tid & 31;
    int wid = tid >> 5;   // 0..15
    int wy = wid >> 2;    // 0..3 -> M sub-block (32 rows)
    int wx = wid & 3;     // 0..3 -> N sub-block (64 cols)

    // Pair decode
    int pairIdx = blockIdx.x;
    const __nv_bfloat16* A;
    const __nv_bfloat16* B;
    bool is_nn;
    if (pairIdx < NN_PAIRS) {
        is_nn = true;
        int i, j;
        decode_tri(pairIdx, i, j);
        A = g_n1b + (size_t)i * kP * kD;
        B = g_n1b + (size_t)j * kP * kD;
    } else {
        is_nn = false;
        int t = pairIdx - NN_PAIRS;
        A = g_n1b + (size_t)(t / kM) * kP * kD;
        B = g_n2b + (size_t)(t % kM) * kP * kD;
    }

    if (tid < 256) s_colmax[tid] = -1e30f;
    __syncthreads();

    // cp.async staging: per chunk, A = 128 rows x 8 segs (1024), B = 256 rows (2048).
    // 512 threads: A 2 segs/thread, B 4 segs/thread. seg s: row = s>>3, sub = s&7.
    int ldRow = tid >> 3;               // 0..63
    int ldSeg = (tid & 7) * 8;          // halves offset within 64-half window

    uint32_t smA[2] = { smem_u32(sm + OFF_A0), smem_u32(sm + OFF_A1) };
    uint32_t smB[2] = { smem_u32(sm + OFF_B0), smem_u32(sm + OFF_B1) };
    uint32_t dOff[4];
    #pragma unroll
    for (int it = 0; it < 4; it++)
        dOff[it] = (uint32_t)(((ldRow + it * 64) * STRIDE + ldSeg) * 2);

    // ldmatrix lane addressing (byte offsets within a staging buffer)
    int ar = lane & 15, ah = lane >> 4;
    uint32_t aOffB = (uint32_t)(((wy * 32 + ar) * STRIDE + ah * 8) * 2);
    int bq = lane >> 3, brr = lane & 7;
    uint32_t bOffB = (uint32_t)(((wx * 64 + ((bq >> 1) & 1) * 8 + brr) * STRIDE + (bq & 1) * 8) * 2);

    // N-tile validity at 16-col granularity (uniform per warp; fixed for pair)
    bool nval[4];
    #pragma unroll
    for (int ntp = 0; ntp < 4; ntp++) nval[ntp] = (wx * 64 + ntp * 16) < kP;

    #pragma unroll 1
    for (int mb = 0; mb < 2; mb++) {
        int am0 = mb * 128;
        // M-tile validity at 16-row granularity (uniform per warp)
        bool mval[2];
        #pragma unroll
        for (int mt = 0; mt < 2; mt++) mval[mt] = (am0 + wy * 32 + mt * 16) < kP;
        bool anyM = mval[0];

        float acc[2][8][4];
        #pragma unroll
        for (int mt = 0; mt < 2; mt++)
            #pragma unroll
            for (int nt = 0; nt < 8; nt++)
                #pragma unroll
                for (int e = 0; e < 4; e++) acc[mt][nt][e] = 0.0f;

        // Preload chunk 0 into buffer 0
        {
            #pragma unroll
            for (int it = 0; it < 2; it++) {
                int r = am0 + ldRow + it * 64;
                cpa16(smA[0] + dOff[it], A + (size_t)r * kD + ldSeg, r < kP);
            }
            #pragma unroll
            for (int it = 0; it < 4; it++) {
                int r = ldRow + it * 64;
                cpa16(smB[0] + dOff[it], B + (size_t)r * kD + ldSeg, r < kP);
            }
            CPA_COMMIT();
        }

        #pragma unroll 1
        for (int c = 0; c < NCHUNK; c++) {
            int b = c & 1;
            CPA_WAIT0();
            __syncthreads();   // buf c ready; all warps past mma(c-1)

            if (c + 1 < NCHUNK) {
                int nbuf = (c + 1) & 1;
                int k0 = (c + 1) * KC + ldSeg;
                #pragma unroll
                for (int it = 0; it < 2; it++) {
                    int r = am0 + ldRow + it * 64;
                    cpa16(smA[nbuf] + dOff[it], A + (size_t)r * kD + k0, r < kP);
                }
                #pragma unroll
                for (int it = 0; it < 4; it++) {
                    int r = ldRow + it * 64;
                    cpa16(smB[nbuf] + dOff[it], B + (size_t)r * kD + k0, r < kP);
                }
                CPA_COMMIT();
            }

            if (anyM) {
                #pragma unroll
                for (int ks = 0; ks < 4; ks++) {
                    uint32_t a0[2][4];
                    #pragma unroll
                    for (int mt = 0; mt < 2; mt++)
                        if (mval[mt])
                            ldmatrix_x4(a0[mt][0], a0[mt][1], a0[mt][2], a0[mt][3],
                                        smA[b] + aOffB + (uint32_t)((mt * 16 * STRIDE + ks * 16) * 2));
                    #pragma unroll
                    for (int ntp = 0; ntp < 4; ntp++) {
                        if (nval[ntp]) {
                            uint32_t b0, b1, b2, b3;
                            ldmatrix_x4(b0, b1, b2, b3,
                                        smB[b] + bOffB + (uint32_t)((ntp * 16 * STRIDE + ks * 16) * 2));
                            #pragma unroll
                            for (int mt = 0; mt < 2; mt++) {
                                if (mval[mt]) {
                                    mma_bf16(acc[mt][ntp * 2 + 0], a0[mt], b0, b1);
                                    mma_bf16(acc[mt][ntp * 2 + 1], a0[mt], b2, b3);
                                }
                            }
                        }
                    }
                }
            }
        }
        __syncthreads();   // all mma done before s_part reuse

        // ----- Epilogue: column max over this pass's valid rows -----
        int rbase = am0 + wy * 32 + (lane >> 2);
        #pragma unroll
        for (int nt = 0; nt < 8; nt++) {
            if (!nval[nt >> 1]) continue;   // uniform per warp; those cols never read
            float c0 = -1e30f, c1 = -1e30f;
            #pragma unroll
            for (int mt = 0; mt < 2; mt++) {
                int r1 = rbase + mt * 16;
                bool v1 = r1 < kP, v2 = (r1 + 8) < kP;
                const float* cc = acc[mt][nt];
                c0 = fmaxf(c0, fmaxf(v1 ? cc[0] : -1e30f, v2 ? cc[2] : -1e30f));
                c1 = fmaxf(c1, fmaxf(v1 ? cc[1] : -1e30f, v2 ? cc[3] : -1e30f));
            }
            #pragma unroll
            for (int o = 4; o <= 16; o <<= 1) {
                c0 = fmaxf(c0, __shfl_xor_sync(0xffffffffu, c0, o));
                c1 = fmaxf(c1, __shfl_xor_sync(0xffffffffu, c1, o));
            }
            if (lane < 4) {
                int col = wx * 64 + nt * 8 + 2 * lane;
                s_part[wy * 256 + col]     = c0;
                s_part[wy * 256 + col + 1] = c1;
            }
        }
        __syncthreads();
        if (tid < 256 && tid < kP) {
            float m = fmaxf(fmaxf(s_part[0 * 256 + tid], s_part[1 * 256 + tid]),
                            fmaxf(s_part[2 * 256 + tid], s_part[3 * 256 + tid]));
            s_colmax[tid] = fmaxf(s_colmax[tid], m);
        }
        __syncthreads();
    }

    // ----- Loss over q < 196, warp-shuffle block reduce -----
    float v = 0.0f;
    if (tid < kP) {
        float m = s_colmax[tid];
        v = is_nn ? (1.0f - m) : fmaxf(m - kMargin, 0.0f);
    }
    #pragma unroll
    for (int o = 16; o > 0; o >>= 1) v += __shfl_xor_sync(0xffffffffu, v, o);
    if (lane == 0) s_rbuf[wid] = v;
    __syncthreads();
    if (tid == 0) {
        float tot = 0.f;
        #pragma unroll
        for (int w = 0; w < 16; w++) tot += s_rbuf[w];
        g_pair_loss[pairIdx] = tot;
    }
}

// ---------------------------------------------------------------------------
// Kernel 3: deterministic finalize
// ---------------------------------------------------------------------------
__global__ void finalize_kernel(float* __restrict__ out) {
    int t = threadIdx.x;
    float pos = 0.f, neg = 0.f;
    for (int idx = t; idx < TOTAL_PAIRS; idx += 256) {
        float v = g_pair_loss[idx];
        if (idx < NN_PAIRS) pos += v; else neg += v;
    }
    #pragma unroll
    for (int o = 16; o > 0; o >>= 1) {
        pos += __shfl_xor_sync(0xffffffffu, pos, o);
        neg += __shfl_xor_sync(0xffffffffu, neg, o);
    }
    __shared__ float sp[8], sn[8];
    if ((t & 31) == 0) { sp[t >> 5] = pos; sn[t >> 5] = neg; }
    __syncthreads();
    if (t == 0) {
        float ptot = 0.f, ntot = 0.f;
        #pragma unroll
        for (int w = 0; w < 8; w++) { ptot += sp[w]; ntot += sn[w]; }
        out[0] = ptot / (float)(NN_PAIRS * kP) + ntot / (float)(kN * kM * kP);
    }
}

// ---------------------------------------------------------------------------
extern "C" void kernel_launch(void* const* d_in, const int* in_sizes, int n_in,
                              void* d_out, int out_size) {
    const float* normal = (const float*)d_in[0];
    const float* defect = (const float*)d_in[1];
    float* out = (float*)d_out;

    cudaFuncSetAttribute(pair_kernel, cudaFuncAttributeMaxDynamicSharedMemorySize, SMEM_BYTES);

    normalize_kernel<<<(kN + kM) * kP / 8, 256>>>(normal, defect);
    pair_kernel<<<TOTAL_PAIRS, 512, SMEM_BYTES>>>();
    finalize_kernel<<<1, 256>>>(out);
}

// round 16
// speedup vs baseline: 1.0988x; 1.0255x over previous
#include <cuda_runtime.h>
#include <cuda_bf16.h>
#include <math.h>
#include <stdint.h>

// ---------------------------------------------------------------------------
// Problem constants
// ---------------------------------------------------------------------------
static constexpr int kN = 32;
static constexpr int kM = 32;
static constexpr int kP = 196;
static constexpr int kD = 768;
static constexpr float kMargin = 0.5f;
static constexpr float kEps = 1e-8f;

static constexpr int NN_PAIRS = kN * (kN - 1) / 2;      // 496
static constexpr int ND_PAIRS = kN * kM;                // 1024
static constexpr int TOTAL_PAIRS = NN_PAIRS + ND_PAIRS; // 1520

static constexpr int KC = 128;           // k-chunk in bf16 halves (8 ks-steps)
static constexpr int NCHUNK = kD / KC;   // 6
static constexpr int STRIDE = 136;       // smem row stride in halves (272B: conflict-free ldmatrix)

// Dynamic smem layout (bytes): 2-stage A(128 rows)/B(256 rows) + scratch
static constexpr int A_BYTES    = 128 * STRIDE * 2;              // 34816
static constexpr int B_BYTES    = 256 * STRIDE * 2;              // 69632
static constexpr int OFF_A0     = 0;
static constexpr int OFF_A1     = OFF_A0 + A_BYTES;              // 34816
static constexpr int OFF_B0     = OFF_A1 + A_BYTES;              // 69632
static constexpr int OFF_B1     = OFF_B0 + B_BYTES;              // 139264
static constexpr int OFF_PART   = OFF_B1 + B_BYTES;              // 208896: float[4][256]
static constexpr int OFF_CMAX   = OFF_PART + 4096;               // 212992: float[256]
static constexpr int OFF_RBUF   = OFF_CMAX + 1024;               // 214016: float[16]
static constexpr int SMEM_BYTES = OFF_RBUF + 64;                 // 214080

// Scratch (device globals — no allocations). 16B-aligned for vector access.
__device__ __align__(16) __nv_bfloat16 g_n1b[kN * kP * kD];
__device__ __align__(16) __nv_bfloat16 g_n2b[kM * kP * kD];
__device__ float g_pair_loss[TOTAL_PAIRS];

// ---------------------------------------------------------------------------
__device__ __forceinline__ uint32_t smem_u32(const void* p) {
    uint32_t a;
    asm("{ .reg .u64 t; cvta.to.shared.u64 t, %1; cvt.u32.u64 %0, t; }" : "=r"(a) : "l"(p));
    return a;
}

__device__ __forceinline__ void ldmatrix_x4(uint32_t& r0, uint32_t& r1,
                                            uint32_t& r2, uint32_t& r3, uint32_t addr) {
    asm volatile("ldmatrix.sync.aligned.m8n8.x4.shared.b16 {%0,%1,%2,%3}, [%4];"
                 : "=r"(r0), "=r"(r1), "=r"(r2), "=r"(r3) : "r"(addr));
}

__device__ __forceinline__ void mma_bf16(float* d, const uint32_t* a, uint32_t b0, uint32_t b1) {
    asm volatile(
        "mma.sync.aligned.m16n8k16.row.col.f32.bf16.bf16.f32 "
        "{%0,%1,%2,%3}, {%4,%5,%6,%7}, {%8,%9}, {%0,%1,%2,%3};"
        : "+f"(d[0]), "+f"(d[1]), "+f"(d[2]), "+f"(d[3])
        : "r"(a[0]), "r"(a[1]), "r"(a[2]), "r"(a[3]), "r"(b0), "r"(b1));
}

// cp.async 16B with zero-fill when invalid (src-size form)
__device__ __forceinline__ void cpa16(uint32_t dst, const void* src, bool valid) {
    int sz = valid ? 16 : 0;
    asm volatile("cp.async.cg.shared.global [%0], [%1], 16, %2;"
                 :: "r"(dst), "l"(src), "r"(sz) : "memory");
}
#define CPA_COMMIT() asm volatile("cp.async.commit_group;" ::: "memory")
#define CPA_WAIT0()  asm volatile("cp.async.wait_group 0;" ::: "memory")

// ---------------------------------------------------------------------------
// Kernel 1: one warp per row L2 normalize, fp32 -> bf16 (no block barriers)
// ---------------------------------------------------------------------------
__global__ void normalize_kernel(const float* __restrict__ normal,
                                 const float* __restrict__ defect) {
    int row = (blockIdx.x * blockDim.x + threadIdx.x) >> 5;   // global warp id
    int lane = threadIdx.x & 31;

    const float* src;
    __nv_bfloat16* dst;
    if (row < kN * kP) {
        src = normal + (size_t)row * kD;
        dst = g_n1b + (size_t)row * kD;
    } else {
        int r = row - kN * kP;
        src = defect + (size_t)r * kD;
        dst = g_n2b + (size_t)r * kD;
    }

    float4 v[6];
    float ss = 0.f;
    #pragma unroll
    for (int k = 0; k < 6; k++) {
        v[k] = *(const float4*)(src + lane * 4 + k * 128);
        ss += v[k].x * v[k].x + v[k].y * v[k].y + v[k].z * v[k].z + v[k].w * v[k].w;
    }
    #pragma unroll
    for (int o = 16; o > 0; o >>= 1) ss += __shfl_xor_sync(0xffffffffu, ss, o);
    float s = 1.0f / (sqrtf(ss) + kEps);

    #pragma unroll
    for (int k = 0; k < 6; k++) {
        __nv_bfloat162 h0 = __floats2bfloat162_rn(v[k].x * s, v[k].y * s);
        __nv_bfloat162 h1 = __floats2bfloat162_rn(v[k].z * s, v[k].w * s);
        uint2 pk = make_uint2(*(uint32_t*)&h0, *(uint32_t*)&h1);
        *(uint2*)(dst + lane * 4 + k * 128) = pk;
    }
}

// ---------------------------------------------------------------------------
__device__ __forceinline__ void decode_tri(int t, int& i, int& j) {
    float disc = (float)((2 * kN - 1) * (2 * kN - 1) - 8 * t);
    int ii = (int)((2.0f * kN - 1.0f - sqrtf(disc)) * 0.5f);
    while (ii > 0 && t < ii * (2 * kN - ii - 1) / 2) ii--;
    while (t >= (ii + 1) * (2 * kN - ii - 2) / 2 + (ii + 1)) ii++;
    int base = ii * (2 * kN - ii - 1) / 2;
    i = ii;
    j = ii + 1 + (t - base);
}

// ---------------------------------------------------------------------------
// Kernel 2: ONE 512-thread CTA per pair. Block covers 128(M) x 256(N) per
// pass, 2 mb passes. Warp grid 4(wy) x 4(wx), warp tile 32x64
// (2 mt x 8 nt m16n8 frags). KC=128 chunks -> 12 sync iterations per pair.
// ---------------------------------------------------------------------------
__global__ void __launch_bounds__(512, 1) pair_kernel() {
    extern __shared__ __align__(16) char sm[];
    float* s_part   = (float*)(sm + OFF_PART);   // [4][256]
    float* s_colmax = (float*)(sm + OFF_CMAX);   // [256]
    float* s_rbuf   = (float*)(sm + OFF_RBUF);   // [16]

    int tid = threadIdx.x;
    int lane = tid & 31;
    int wid = tid >> 5;   // 0..15
    int wy = wid >> 2;    // 0..3 -> M sub-block (32 rows)
    int wx = wid & 3;     // 0..3 -> N sub-block (64 cols)

    // Pair decode
    int pairIdx = blockIdx.x;
    const __nv_bfloat16* A;
    const __nv_bfloat16* B;
    bool is_nn;
    if (pairIdx < NN_PAIRS) {
        is_nn = true;
        int i, j;
        decode_tri(pairIdx, i, j);
        A = g_n1b + (size_t)i * kP * kD;
        B = g_n1b + (size_t)j * kP * kD;
    } else {
        is_nn = false;
        int t = pairIdx - NN_PAIRS;
        A = g_n1b + (size_t)(t / kM) * kP * kD;
        B = g_n2b + (size_t)(t % kM) * kP * kD;
    }

    if (tid < 256) s_colmax[tid] = -1e30f;
    __syncthreads();

    // cp.async staging: per chunk, A = 128 rows x 16 segs = 2048 (4/thread),
    // B = 256 rows x 16 segs = 4096 (8/thread). seg: row = tid>>4 (+32*it),
    // sub-seg = tid & 15.
    int ldRow = tid >> 4;               // 0..31
    int ldSeg = (tid & 15) * 8;         // halves offset within 128-half window

    uint32_t smA[2] = { smem_u32(sm + OFF_A0), smem_u32(sm + OFF_A1) };
    uint32_t smB[2] = { smem_u32(sm + OFF_B0), smem_u32(sm + OFF_B1) };
    uint32_t dOff[8];
    #pragma unroll
    for (int it = 0; it < 8; it++)
        dOff[it] = (uint32_t)(((ldRow + it * 32) * STRIDE + ldSeg) * 2);

    // ldmatrix lane addressing (byte offsets within a staging buffer)
    int ar = lane & 15, ah = lane >> 4;
    uint32_t aOffB = (uint32_t)(((wy * 32 + ar) * STRIDE + ah * 8) * 2);
    int bq = lane >> 3, brr = lane & 7;
    uint32_t bOffB = (uint32_t)(((wx * 64 + ((bq >> 1) & 1) * 8 + brr) * STRIDE + (bq & 1) * 8) * 2);

    // N-tile validity at 16-col granularity (uniform per warp; fixed for pair)
    bool nval[4];
    #pragma unroll
    for (int ntp = 0; ntp < 4; ntp++) nval[ntp] = (wx * 64 + ntp * 16) < kP;

    #pragma unroll 1
    for (int mb = 0; mb < 2; mb++) {
        int am0 = mb * 128;
        // M-tile validity at 16-row granularity (uniform per warp)
        bool mval[2];
        #pragma unroll
        for (int mt = 0; mt < 2; mt++) mval[mt] = (am0 + wy * 32 + mt * 16) < kP;
        bool anyM = mval[0];

        float acc[2][8][4];
        #pragma unroll
        for (int mt = 0; mt < 2; mt++)
            #pragma unroll
            for (int nt = 0; nt < 8; nt++)
                #pragma unroll
                for (int e = 0; e < 4; e++) acc[mt][nt][e] = 0.0f;

        // Preload chunk 0 into buffer 0
        {
            #pragma unroll
            for (int it = 0; it < 4; it++) {
                int r = am0 + ldRow + it * 32;
                cpa16(smA[0] + dOff[it], A + (size_t)r * kD + ldSeg, r < kP);
            }
            #pragma unroll
            for (int it = 0; it < 8; it++) {
                int r = ldRow + it * 32;
                cpa16(smB[0] + dOff[it], B + (size_t)r * kD + ldSeg, r < kP);
            }
            CPA_COMMIT();
        }

        #pragma unroll 1
        for (int c = 0; c < NCHUNK; c++) {
            int b = c & 1;
            CPA_WAIT0();
            __syncthreads();   // buf c ready; all warps past mma(c-1)

            if (c + 1 < NCHUNK) {
                int nbuf = (c + 1) & 1;
                int k0 = (c + 1) * KC + ldSeg;
                #pragma unroll
                for (int it = 0; it < 4; it++) {
                    int r = am0 + ldRow + it * 32;
                    cpa16(smA[nbuf] + dOff[it], A + (size_t)r * kD + k0, r < kP);
                }
                #pragma unroll
                for (int it = 0; it < 8; it++) {
                    int r = ldRow + it * 32;
                    cpa16(smB[nbuf] + dOff[it], B + (size_t)r * kD + k0, r < kP);
                }
                CPA_COMMIT();
            }

            if (anyM) {
                #pragma unroll
                for (int ks = 0; ks < 8; ks++) {
                    uint32_t a0[2][4];
                    #pragma unroll
                    for (int mt = 0; mt < 2; mt++)
                        if (mval[mt])
                            ldmatrix_x4(a0[mt][0], a0[mt][1], a0[mt][2], a0[mt][3],
                                        smA[b] + aOffB + (uint32_t)((mt * 16 * STRIDE + ks * 16) * 2));
                    #pragma unroll
                    for (int ntp = 0; ntp < 4; ntp++) {
                        if (nval[ntp]) {
                            uint32_t b0, b1, b2, b3;
                            ldmatrix_x4(b0, b1, b2, b3,
                                        smB[b] + bOffB + (uint32_t)((ntp * 16 * STRIDE + ks * 16) * 2));
                            #pragma unroll
                            for (int mt = 0; mt < 2; mt++) {
                                if (mval[mt]) {
                                    mma_bf16(acc[mt][ntp * 2 + 0], a0[mt], b0, b1);
                                    mma_bf16(acc[mt][ntp * 2 + 1], a0[mt], b2, b3);
                                }
                            }
                        }
                    }
                }
            }
        }
        __syncthreads();   // all mma done before s_part reuse

        // ----- Epilogue: column max over this pass's valid rows -----
        int rbase = am0 + wy * 32 + (lane >> 2);
        #pragma unroll
        for (int nt = 0; nt < 8; nt++) {
            if (!nval[nt >> 1]) continue;   // uniform per warp; those cols never read
            float c0 = -1e30f, c1 = -1e30f;
            #pragma unroll
            for (int mt = 0; mt < 2; mt++) {
                int r1 = rbase + mt * 16;
                bool v1 = r1 < kP, v2 = (r1 + 8) < kP;
                const float* cc = acc[mt][nt];
                c0 = fmaxf(c0, fmaxf(v1 ? cc[0] : -1e30f, v2 ? cc[2] : -1e30f));
                c1 = fmaxf(c1, fmaxf(v1 ? cc[1] : -1e30f, v2 ? cc[3] : -1e30f));
            }
            #pragma unroll
            for (int o = 4; o <= 16; o <<= 1) {
                c0 = fmaxf(c0, __shfl_xor_sync(0xffffffffu, c0, o));
                c1 = fmaxf(c1, __shfl_xor_sync(0xffffffffu, c1, o));
            }
            if (lane < 4) {
                int col = wx * 64 + nt * 8 + 2 * lane;
                s_part[wy * 256 + col]     = c0;
                s_part[wy * 256 + col + 1] = c1;
            }
        }
        __syncthreads();
        if (tid < 256 && tid < kP) {
            float m = fmaxf(fmaxf(s_part[0 * 256 + tid], s_part[1 * 256 + tid]),
                            fmaxf(s_part[2 * 256 + tid], s_part[3 * 256 + tid]));
            s_colmax[tid] = fmaxf(s_colmax[tid], m);
        }
        __syncthreads();
    }

    // ----- Loss over q < 196, warp-shuffle block reduce -----
    float v = 0.0f;
    if (tid < kP) {
        float m = s_colmax[tid];
        v = is_nn ? (1.0f - m) : fmaxf(m - kMargin, 0.0f);
    }
    #pragma unroll
    for (int o = 16; o > 0; o >>= 1) v += __shfl_xor_sync(0xffffffffu, v, o);
    if (lane == 0) s_rbuf[wid] = v;
    __syncthreads();
    if (tid == 0) {
        float tot = 0.f;
        #pragma unroll
        for (int w = 0; w < 16; w++) tot += s_rbuf[w];
        g_pair_loss[pairIdx] = tot;
    }
}

// ---------------------------------------------------------------------------
// Kernel 3: deterministic finalize
// ---------------------------------------------------------------------------
__global__ void finalize_kernel(float* __restrict__ out) {
    int t = threadIdx.x;
    float pos = 0.f, neg = 0.f;
    for (int idx = t; idx < TOTAL_PAIRS; idx += 256) {
        float v = g_pair_loss[idx];
        if (idx < NN_PAIRS) pos += v; else neg += v;
    }
    #pragma unroll
    for (int o = 16; o > 0; o >>= 1) {
        pos += __shfl_xor_sync(0xffffffffu, pos, o);
        neg += __shfl_xor_sync(0xffffffffu, neg, o);
    }
    __shared__ float sp[8], sn[8];
    if ((t & 31) == 0) { sp[t >> 5] = pos; sn[t >> 5] = neg; }
    __syncthreads();
    if (t == 0) {
        float ptot = 0.f, ntot = 0.f;
        #pragma unroll
        for (int w = 0; w < 8; w++) { ptot += sp[w]; ntot += sn[w]; }
        out[0] = ptot / (float)(NN_PAIRS * kP) + ntot / (float)(kN * kM * kP);
    }
}

// ---------------------------------------------------------------------------
extern "C" void kernel_launch(void* const* d_in, const int* in_sizes, int n_in,
                              void* d_out, int out_size) {
    const float* normal = (const float*)d_in[0];
    const float* defect = (const float*)d_in[1];
    float* out = (float*)d_out;

    cudaFuncSetAttribute(pair_kernel, cudaFuncAttributeMaxDynamicSharedMemorySize, SMEM_BYTES);

    normalize_kernel<<<(kN + kM) * kP / 8, 256>>>(normal, defect);
    pair_kernel<<<TOTAL_PAIRS, 512, SMEM_BYTES>>>();
    finalize_kernel<<<1, 256>>>(out);
}

// round 17
// speedup vs baseline: 1.1011x; 1.0021x over previous
#include <cuda_runtime.h>
#include <cuda_fp16.h>
#include <math.h>
#include <stdint.h>

// ---------------------------------------------------------------------------
// Problem constants
// ---------------------------------------------------------------------------
static constexpr int kN = 32;
static constexpr int kM = 32;
static constexpr int kP = 196;
static constexpr int kD = 768;
static constexpr float kMargin = 0.5f;
static constexpr float kEps = 1e-8f;

static constexpr int NN_PAIRS = kN * (kN - 1) / 2;      // 496
static constexpr int ND_PAIRS = kN * kM;                // 1024
static constexpr int TOTAL_PAIRS = NN_PAIRS + ND_PAIRS; // 1520

static constexpr int KC = 128;           // k-chunk in halves (8 ks-steps)
static constexpr int NCHUNK = kD / KC;   // 6
static constexpr int STRIDE = 136;       // smem row stride in halves (272B: conflict-free ldmatrix)

// Dynamic smem layout (bytes): 2-stage A(128 rows)/B(256 rows) + scratch
static constexpr int A_BYTES    = 128 * STRIDE * 2;              // 34816
static constexpr int B_BYTES    = 256 * STRIDE * 2;              // 69632
static constexpr int OFF_A0     = 0;
static constexpr int OFF_A1     = OFF_A0 + A_BYTES;              // 34816
static constexpr int OFF_B0     = OFF_A1 + A_BYTES;              // 69632
static constexpr int OFF_B1     = OFF_B0 + B_BYTES;              // 139264
static constexpr int OFF_PART   = OFF_B1 + B_BYTES;              // 208896: float[4][256]
static constexpr int OFF_CMAX   = OFF_PART + 4096;               // 212992: float[256]
static constexpr int OFF_RBUF   = OFF_CMAX + 1024;               // 214016: float[16]
static constexpr int SMEM_BYTES = OFF_RBUF + 64;                 // 214080

// Scratch (device globals — no allocations). 16B-aligned for vector access.
__device__ __align__(16) __half g_n1h[kN * kP * kD];
__device__ __align__(16) __half g_n2h[kM * kP * kD];
__device__ float g_pair_loss[TOTAL_PAIRS];

// ---------------------------------------------------------------------------
__device__ __forceinline__ uint32_t smem_u32(const void* p) {
    uint32_t a;
    asm("{ .reg .u64 t; cvta.to.shared.u64 t, %1; cvt.u32.u64 %0, t; }" : "=r"(a) : "l"(p));
    return a;
}

__device__ __forceinline__ void ldmatrix_x4(uint32_t& r0, uint32_t& r1,
                                            uint32_t& r2, uint32_t& r3, uint32_t addr) {
    asm volatile("ldmatrix.sync.aligned.m8n8.x4.shared.b16 {%0,%1,%2,%3}, [%4];"
                 : "=r"(r0), "=r"(r1), "=r"(r2), "=r"(r3) : "r"(addr));
}

// fp16 mma with fp16 accumulator: D,C = {2 x b32} (4 halves), A fp16, B fp16.
__device__ __forceinline__ void mma_f16acc(uint32_t* d, const uint32_t* a,
                                           uint32_t b0, uint32_t b1) {
    asm volatile(
        "mma.sync.aligned.m16n8k16.row.col.f16.f16.f16.f16 "
        "{%0,%1}, {%2,%3,%4,%5}, {%6,%7}, {%0,%1};"
        : "+r"(d[0]), "+r"(d[1])
        : "r"(a[0]), "r"(a[1]), "r"(a[2]), "r"(a[3]), "r"(b0), "r"(b1));
}

// cp.async 16B with zero-fill when invalid (src-size form)
__device__ __forceinline__ void cpa16(uint32_t dst, const void* src, bool valid) {
    int sz = valid ? 16 : 0;
    asm volatile("cp.async.cg.shared.global [%0], [%1], 16, %2;"
                 :: "r"(dst), "l"(src), "r"(sz) : "memory");
}
#define CPA_COMMIT() asm volatile("cp.async.commit_group;" ::: "memory")
#define CPA_WAIT0()  asm volatile("cp.async.wait_group 0;" ::: "memory")

// ---------------------------------------------------------------------------
// Kernel 1: one warp per row L2 normalize, fp32 -> fp16 (no block barriers)
// ---------------------------------------------------------------------------
__global__ void normalize_kernel(const float* __restrict__ normal,
                                 const float* __restrict__ defect) {
    int row = (blockIdx.x * blockDim.x + threadIdx.x) >> 5;   // global warp id
    int lane = threadIdx.x & 31;

    const float* src;
    __half* dst;
    if (row < kN * kP) {
        src = normal + (size_t)row * kD;
        dst = g_n1h + (size_t)row * kD;
    } else {
        int r = row - kN * kP;
        src = defect + (size_t)r * kD;
        dst = g_n2h + (size_t)r * kD;
    }

    float4 v[6];
    float ss = 0.f;
    #pragma unroll
    for (int k = 0; k < 6; k++) {
        v[k] = *(const float4*)(src + lane * 4 + k * 128);
        ss += v[k].x * v[k].x + v[k].y * v[k].y + v[k].z * v[k].z + v[k].w * v[k].w;
    }
    #pragma unroll
    for (int o = 16; o > 0; o >>= 1) ss += __shfl_xor_sync(0xffffffffu, ss, o);
    float s = 1.0f / (sqrtf(ss) + kEps);

    #pragma unroll
    for (int k = 0; k < 6; k++) {
        __half2 h0 = __floats2half2_rn(v[k].x * s, v[k].y * s);
        __half2 h1 = __floats2half2_rn(v[k].z * s, v[k].w * s);
        uint2 pk = make_uint2(*(uint32_t*)&h0, *(uint32_t*)&h1);
        *(uint2*)(dst + lane * 4 + k * 128) = pk;
    }
}

// ---------------------------------------------------------------------------
__device__ __forceinline__ void decode_tri(int t, int& i, int& j) {
    float disc = (float)((2 * kN - 1) * (2 * kN - 1) - 8 * t);
    int ii = (int)((2.0f * kN - 1.0f - sqrtf(disc)) * 0.5f);
    while (ii > 0 && t < ii * (2 * kN - ii - 1) / 2) ii--;
    while (t >= (ii + 1) * (2 * kN - ii - 2) / 2 + (ii + 1)) ii++;
    int base = ii * (2 * kN - ii - 1) / 2;
    i = ii;
    j = ii + 1 + (t - base);
}

// ---------------------------------------------------------------------------
// Kernel 2: ONE 512-thread CTA per pair. fp16 mma.sync (f16 accumulate) GEMM
// + fused column-max + loss. 128(M) x 256(N) per pass, 2 mb passes. Warp grid
// 4(wy) x 4(wx), warp tile 32x64. KC=128 chunks -> 12 sync iterations/pair.
// ---------------------------------------------------------------------------
__global__ void __launch_bounds__(512, 1) pair_kernel() {
    extern __shared__ __align__(16) char sm[];
    float* s_part   = (float*)(sm + OFF_PART);   // [4][256]
    float* s_colmax = (float*)(sm + OFF_CMAX);   // [256]
    float* s_rbuf   = (float*)(sm + OFF_RBUF);   // [16]

    int tid = threadIdx.x;
    int lane = tid & 31;
    int wid = tid >> 5;   // 0..15
    int wy = wid >> 2;    // 0..3 -> M sub-block (32 rows)
    int wx = wid & 3;     // 0..3 -> N sub-block (64 cols)

    // Pair decode
    int pairIdx = blockIdx.x;
    const __half* A;
    const __half* B;
    bool is_nn;
    if (pairIdx < NN_PAIRS) {
        is_nn = true;
        int i, j;
        decode_tri(pairIdx, i, j);
        A = g_n1h + (size_t)i * kP * kD;
        B = g_n1h + (size_t)j * kP * kD;
    } else {
        is_nn = false;
        int t = pairIdx - NN_PAIRS;
        A = g_n1h + (size_t)(t / kM) * kP * kD;
        B = g_n2h + (size_t)(t % kM) * kP * kD;
    }

    if (tid < 256) s_colmax[tid] = -1e30f;
    __syncthreads();

    // cp.async staging: per chunk, A = 2048 segs (4/thread), B = 4096 (8/thread)
    int ldRow = tid >> 4;               // 0..31
    int ldSeg = (tid & 15) * 8;         // halves offset within 128-half window

    uint32_t smA[2] = { smem_u32(sm + OFF_A0), smem_u32(sm + OFF_A1) };
    uint32_t smB[2] = { smem_u32(sm + OFF_B0), smem_u32(sm + OFF_B1) };
    uint32_t dOff[8];
    #pragma unroll
    for (int it = 0; it < 8; it++)
        dOff[it] = (uint32_t)(((ldRow + it * 32) * STRIDE + ldSeg) * 2);

    // ldmatrix lane addressing (byte offsets within a staging buffer)
    int ar = lane & 15, ah = lane >> 4;
    uint32_t aOffB = (uint32_t)(((wy * 32 + ar) * STRIDE + ah * 8) * 2);
    int bq = lane >> 3, brr = lane & 7;
    uint32_t bOffB = (uint32_t)(((wx * 64 + ((bq >> 1) & 1) * 8 + brr) * STRIDE + (bq & 1) * 8) * 2);

    // N-tile validity at 16-col granularity (uniform per warp; fixed for pair)
    bool nval[4];
    #pragma unroll
    for (int ntp = 0; ntp < 4; ntp++) nval[ntp] = (wx * 64 + ntp * 16) < kP;

    #pragma unroll 1
    for (int mb = 0; mb < 2; mb++) {
        int am0 = mb * 128;
        // M-tile validity at 16-row granularity (uniform per warp)
        bool mval[2];
        #pragma unroll
        for (int mt = 0; mt < 2; mt++) mval[mt] = (am0 + wy * 32 + mt * 16) < kP;
        bool anyM = mval[0];

        // fp16 accumulators: 2 b32 regs (4 halves) per m16n8 unit
        uint32_t acc[2][8][2];
        #pragma unroll
        for (int mt = 0; mt < 2; mt++)
            #pragma unroll
            for (int nt = 0; nt < 8; nt++) {
                acc[mt][nt][0] = 0u;
                acc[mt][nt][1] = 0u;
            }

        // Preload chunk 0 into buffer 0
        {
            #pragma unroll
            for (int it = 0; it < 4; it++) {
                int r = am0 + ldRow + it * 32;
                cpa16(smA[0] + dOff[it], A + (size_t)r * kD + ldSeg, r < kP);
            }
            #pragma unroll
            for (int it = 0; it < 8; it++) {
                int r = ldRow + it * 32;
                cpa16(smB[0] + dOff[it], B + (size_t)r * kD + ldSeg, r < kP);
            }
            CPA_COMMIT();
        }

        #pragma unroll 1
        for (int c = 0; c < NCHUNK; c++) {
            int b = c & 1;
            CPA_WAIT0();
            __syncthreads();   // buf c ready; all warps past mma(c-1)

            if (c + 1 < NCHUNK) {
                int nbuf = (c + 1) & 1;
                int k0 = (c + 1) * KC + ldSeg;
                #pragma unroll
                for (int it = 0; it < 4; it++) {
                    int r = am0 + ldRow + it * 32;
                    cpa16(smA[nbuf] + dOff[it], A + (size_t)r * kD + k0, r < kP);
                }
                #pragma unroll
                for (int it = 0; it < 8; it++) {
                    int r = ldRow + it * 32;
                    cpa16(smB[nbuf] + dOff[it], B + (size_t)r * kD + k0, r < kP);
                }
                CPA_COMMIT();
            }

            if (anyM) {
                #pragma unroll
                for (int ks = 0; ks < 8; ks++) {
                    uint32_t a0[2][4];
                    #pragma unroll
                    for (int mt = 0; mt < 2; mt++)
                        if (mval[mt])
                            ldmatrix_x4(a0[mt][0], a0[mt][1], a0[mt][2], a0[mt][3],
                                        smA[b] + aOffB + (uint32_t)((mt * 16 * STRIDE + ks * 16) * 2));
                    #pragma unroll
                    for (int ntp = 0; ntp < 4; ntp++) {
                        if (nval[ntp]) {
                            uint32_t b0, b1, b2, b3;
                            ldmatrix_x4(b0, b1, b2, b3,
                                        smB[b] + bOffB + (uint32_t)((ntp * 16 * STRIDE + ks * 16) * 2));
                            #pragma unroll
                            for (int mt = 0; mt < 2; mt++) {
                                if (mval[mt]) {
                                    mma_f16acc(acc[mt][ntp * 2 + 0], a0[mt], b0, b1);
                                    mma_f16acc(acc[mt][ntp * 2 + 1], a0[mt], b2, b3);
                                }
                            }
                        }
                    }
                }
            }
        }
        __syncthreads();   // all mma done before s_part reuse

        // ----- Epilogue: column max over this pass's valid rows -----
        // f16 acc layout: reg0 = {d0,d1} (row r, cols c/c+1), reg1 = {d2,d3} (row r+8)
        int rbase = am0 + wy * 32 + (lane >> 2);
        #pragma unroll
        for (int nt = 0; nt < 8; nt++) {
            if (!nval[nt >> 1]) continue;   // uniform per warp; those cols never read
            float c0 = -1e30f, c1 = -1e30f;
            #pragma unroll
            for (int mt = 0; mt < 2; mt++) {
                int r1 = rbase + mt * 16;
                bool v1 = r1 < kP, v2 = (r1 + 8) < kP;
                float2 lo = __half22float2(*(const __half2*)&acc[mt][nt][0]);
                float2 hi = __half22float2(*(const __half2*)&acc[mt][nt][1]);
                c0 = fmaxf(c0, fmaxf(v1 ? lo.x : -1e30f, v2 ? hi.x : -1e30f));
                c1 = fmaxf(c1, fmaxf(v1 ? lo.y : -1e30f, v2 ? hi.y : -1e30f));
            }
            #pragma unroll
            for (int o = 4; o <= 16; o <<= 1) {
                c0 = fmaxf(c0, __shfl_xor_sync(0xffffffffu, c0, o));
                c1 = fmaxf(c1, __shfl_xor_sync(0xffffffffu, c1, o));
            }
            if (lane < 4) {
                int col = wx * 64 + nt * 8 + 2 * lane;
                s_part[wy * 256 + col]     = c0;
                s_part[wy * 256 + col + 1] = c1;
            }
        }
        __syncthreads();
        if (tid < 256 && tid < kP) {
            float m = fmaxf(fmaxf(s_part[0 * 256 + tid], s_part[1 * 256 + tid]),
                            fmaxf(s_part[2 * 256 + tid], s_part[3 * 256 + tid]));
            s_colmax[tid] = fmaxf(s_colmax[tid], m);
        }
        __syncthreads();
    }

    // ----- Loss over q < 196, warp-shuffle block reduce -----
    float v = 0.0f;
    if (tid < kP) {
        float m = s_colmax[tid];
        v = is_nn ? (1.0f - m) : fmaxf(m - kMargin, 0.0f);
    }
    #pragma unroll
    for (int o = 16; o > 0; o >>= 1) v += __shfl_xor_sync(0xffffffffu, v, o);
    if (lane == 0) s_rbuf[wid] = v;
    __syncthreads();
    if (tid == 0) {
        float tot = 0.f;
        #pragma unroll
        for (int w = 0; w < 16; w++) tot += s_rbuf[w];
        g_pair_loss[pairIdx] = tot;
    }
}

// ---------------------------------------------------------------------------
// Kernel 3: deterministic finalize
// ---------------------------------------------------------------------------
__global__ void finalize_kernel(float* __restrict__ out) {
    int t = threadIdx.x;
    float pos = 0.f, neg = 0.f;
    for (int idx = t; idx < TOTAL_PAIRS; idx += 256) {
        float v = g_pair_loss[idx];
        if (idx < NN_PAIRS) pos += v; else neg += v;
    }
    #pragma unroll
    for (int o = 16; o > 0; o >>= 1) {
        pos += __shfl_xor_sync(0xffffffffu, pos, o);
        neg += __shfl_xor_sync(0xffffffffu, neg, o);
    }
    __shared__ float sp[8], sn[8];
    if ((t & 31) == 0) { sp[t >> 5] = pos; sn[t >> 5] = neg; }
    __syncthreads();
    if (t == 0) {
        float ptot = 0.f, ntot = 0.f;
        #pragma unroll
        for (int w = 0; w < 8; w++) { ptot += sp[w]; ntot += sn[w]; }
        out[0] = ptot / (float)(NN_PAIRS * kP) + ntot / (float)(kN * kM * kP);
    }
}

// ---------------------------------------------------------------------------
extern "C" void kernel_launch(void* const* d_in, const int* in_sizes, int n_in,
                              void* d_out, int out_size) {
    const float* normal = (const float*)d_in[0];
    const float* defect = (const float*)d_in[1];
    float* out = (float*)d_out;

    cudaFuncSetAttribute(pair_kernel, cudaFuncAttributeMaxDynamicSharedMemorySize, SMEM_BYTES);

    normalize_kernel<<<(kN + kM) * kP / 8, 256>>>(normal, defect);
    pair_kernel<<<TOTAL_PAIRS, 512, SMEM_BYTES>>>();
    finalize_kernel<<<1, 256>>>(out);
}